// round 1
// baseline (speedup 1.0000x reference)
#include <cuda_runtime.h>

#define B_ 2
#define L_ 1024
#define D_ 768
#define H_ 12
#define DH_ 64
#define NS_ 5
#define PAD 65

// Scratch (static device arrays: allocation-free per harness rules)
__device__ float g_Q[B_*H_*L_*DH_];
__device__ float g_K[B_*H_*L_*DH_];
__device__ float g_V[B_*H_*L_*DH_];
__device__ float g_QW[NS_*B_*H_*L_*DH_];

// ---------------------------------------------------------------------------
// Kernel 1: QKV projections.  X[2048,768] @ W[768,768] + b, output in
// head-major layout  g_{Q,K,V}[b][h][l][d].
// 128x128x8 tile, 256 threads, 8x8 register tiles.
// ---------------------------------------------------------------------------
__global__ __launch_bounds__(256) void qkv_proj_kernel(
    const float* __restrict__ X,
    const float* __restrict__ Wq, const float* __restrict__ bq,
    const float* __restrict__ Wk, const float* __restrict__ bk,
    const float* __restrict__ Wv, const float* __restrict__ bv)
{
    __shared__ float a_s[8][132];   // [k][m], padded
    __shared__ float b_s[8][128];   // [k][n]

    const int z = blockIdx.z;
    const float* W    = (z == 0) ? Wq : ((z == 1) ? Wk : Wv);
    const float* bias = (z == 0) ? bq : ((z == 1) ? bk : bv);
    float* dst        = (z == 0) ? g_Q : ((z == 1) ? g_K : g_V);

    const int tid = threadIdx.x;
    const int tx = tid & 15, ty = tid >> 4;
    const int m0 = blockIdx.y * 128, n0 = blockIdx.x * 128;

    const int arow = tid >> 1;          // 0..127
    const int acol = (tid & 1) * 4;     // 0 or 4
    const int brow = tid >> 5;          // 0..7
    const int bcol = (tid & 31) * 4;    // 0..124

    float acc[8][8];
#pragma unroll
    for (int i = 0; i < 8; i++)
#pragma unroll
        for (int j = 0; j < 8; j++) acc[i][j] = 0.f;

    for (int kt = 0; kt < D_; kt += 8) {
        float4 av  = *(const float4*)&X[(m0 + arow) * D_ + kt + acol];
        float4 bvv = *(const float4*)&W[(kt + brow) * D_ + n0 + bcol];
        __syncthreads();
        a_s[acol + 0][arow] = av.x;
        a_s[acol + 1][arow] = av.y;
        a_s[acol + 2][arow] = av.z;
        a_s[acol + 3][arow] = av.w;
        *(float4*)&b_s[brow][bcol] = bvv;
        __syncthreads();
#pragma unroll
        for (int kk = 0; kk < 8; kk++) {
            float af[8], bf[8];
#pragma unroll
            for (int i = 0; i < 8; i++) af[i] = a_s[kk][ty * 8 + i];
#pragma unroll
            for (int j = 0; j < 8; j++) bf[j] = b_s[kk][tx * 8 + j];
#pragma unroll
            for (int i = 0; i < 8; i++)
#pragma unroll
                for (int j = 0; j < 8; j++) acc[i][j] += af[i] * bf[j];
        }
    }

#pragma unroll
    for (int i = 0; i < 8; i++) {
        int mg = m0 + ty * 8 + i;
        int bb = mg >> 10, l = mg & 1023;
#pragma unroll
        for (int j = 0; j < 8; j++) {
            int ng = n0 + tx * 8 + j;
            int h = ng >> 6, e = ng & 63;
            dst[((bb * H_ + h) * L_ + l) * DH_ + e] = acc[i][j] + bias[ng];
        }
    }
}

// ---------------------------------------------------------------------------
// Kernel 2: qw_i[b,h,l,e] = sum_d q[b,h,l,d] * ssan_w[i,h,d,e]
// grid (rowtile 32, h 12, i 5), 256 threads, 4x4 register tiles.
// ---------------------------------------------------------------------------
__global__ __launch_bounds__(256) void qw_proj_kernel(const float* __restrict__ ssan_w)
{
    __shared__ float q_s[64][PAD];
    __shared__ float w_s[64][PAD];  // w_s[d][e]

    const int si = blockIdx.z, h = blockIdx.y, bt = blockIdx.x;
    const int tid = threadIdx.x;
    const int tx = tid & 15, ty = tid >> 4;

    for (int idx = tid; idx < 64 * 64; idx += 256) {
        int r = idx >> 6, d = idx & 63;
        int gr = bt * 64 + r;
        int bb = gr >> 10, l = gr & 1023;
        q_s[r][d] = g_Q[((bb * H_ + h) * L_ + l) * DH_ + d];
        w_s[r][d] = ssan_w[((si * H_ + h) * DH_ + r) * DH_ + d];
    }
    __syncthreads();

    float acc[4][4];
#pragma unroll
    for (int i = 0; i < 4; i++)
#pragma unroll
        for (int j = 0; j < 4; j++) acc[i][j] = 0.f;

#pragma unroll 8
    for (int dd = 0; dd < 64; dd++) {
        float qf[4], wf[4];
#pragma unroll
        for (int i = 0; i < 4; i++) qf[i] = q_s[ty * 4 + i][dd];
#pragma unroll
        for (int j = 0; j < 4; j++) wf[j] = w_s[dd][tx * 4 + j];
#pragma unroll
        for (int i = 0; i < 4; i++)
#pragma unroll
            for (int j = 0; j < 4; j++) acc[i][j] += qf[i] * wf[j];
    }

#pragma unroll
    for (int i = 0; i < 4; i++) {
        int gr = bt * 64 + ty * 4 + i;
        int bb = gr >> 10, l = gr & 1023;
#pragma unroll
        for (int j = 0; j < 4; j++) {
            int e = tx * 4 + j;
            g_QW[(((si * B_ + bb) * H_ + h) * L_ + l) * DH_ + e] = acc[i][j];
        }
    }
}

// ---------------------------------------------------------------------------
// Kernel 3: fused flash-style attention with relative-position band and
// 5 struct-masked SSAN bias GEMMs. One CTA per (b, h, 64-row q-tile).
// 256 threads (16x16), 4x4 register tiles per phase.
// ---------------------------------------------------------------------------
// smem layout (floats):
#define OFF_Q   0
#define OFF_QW  (64 * PAD)
#define OFF_K   (OFF_QW + 5 * 64 * PAD)
#define OFF_V   (OFF_K + 64 * PAD)
#define OFF_DB  (OFF_V + 64 * PAD)
#define OFF_S   (OFF_DB + 127 * PAD)
#define OFF_RM  (OFF_S + 64 * PAD)
#define OFF_RS  (OFF_RM + 64)
#define OFF_RF  (OFF_RS + 64)
#define SMEM_FLOATS (OFF_RF + 64)

__global__ __launch_bounds__(256) void attn_kernel(
    const float* __restrict__ mask,       // [B,1,1,L]
    const float* __restrict__ strm,       // [5,B,1,L,L]
    const float* __restrict__ dist,       // [2047, 64]
    const float* __restrict__ abs_bias,   // [5, H]
    float* __restrict__ out)              // [B, L, 768]
{
    extern __shared__ float sm[];
    float* q_s  = sm + OFF_Q;
    float* qw_s = sm + OFF_QW;
    float* k_s  = sm + OFF_K;
    float* v_s  = sm + OFF_V;
    float* db_s = sm + OFF_DB;
    float* s_s  = sm + OFF_S;
    float* row_m = sm + OFF_RM;
    float* row_s = sm + OFF_RS;
    float* row_f = sm + OFF_RF;

    const int qt = blockIdx.x, h = blockIdx.y, b = blockIdx.z;
    const int tid = threadIdx.x;
    const int tx = tid & 15, ty = tid >> 4;
    const int ql0 = qt * 64;
    const int bh = b * H_ + h;

    // load q tile + 5 qw tiles (persistent)
    for (int idx = tid; idx < 64 * 64; idx += 256) {
        int l = idx >> 6, d = idx & 63;
        q_s[l * PAD + d] = g_Q[(bh * L_ + ql0 + l) * DH_ + d];
    }
    for (int idx = tid; idx < 5 * 64 * 64; idx += 256) {
        int si = idx >> 12;
        int rem = idx & 4095;
        int l = rem >> 6, d = rem & 63;
        qw_s[(si * 64 + l) * PAD + d] =
            g_QW[si * (B_ * H_ * L_ * DH_) + (bh * L_ + ql0 + l) * DH_ + d];
    }
    if (tid < 64) {
        row_m[tid] = -__int_as_float(0x7f800000);  // -inf
        row_s[tid] = 0.f;
    }

    float o[4][4];
#pragma unroll
    for (int i = 0; i < 4; i++)
#pragma unroll
        for (int j = 0; j < 4; j++) o[i][j] = 0.f;

    __syncthreads();

    for (int kt = 0; kt < 16; kt++) {
        const int kr0 = kt * 64;
        // stage k, v tiles
        for (int idx = tid; idx < 64 * 64; idx += 256) {
            int r = idx >> 6, d = idx & 63;
            k_s[r * PAD + d] = g_K[(bh * L_ + kr0 + r) * DH_ + d];
            v_s[r * PAD + d] = g_V[(bh * L_ + kr0 + r) * DH_ + d];
        }
        // stage dist band: m = l - r + 1023 = m0 + (li - ri + 63)
        const int m0 = ql0 - kr0 + 960;
        for (int idx = tid; idx < 127 * 64; idx += 256) {
            int j = idx >> 6, d = idx & 63;
            db_s[j * PAD + d] = dist[(m0 + j) * DH_ + d];
        }
        __syncthreads();

        // --- pass A: q.k + q.dist + k.dist ---
        float aqk[4][4], aqd[4][4], akd[4][4];
#pragma unroll
        for (int i = 0; i < 4; i++)
#pragma unroll
            for (int j = 0; j < 4; j++) { aqk[i][j] = 0.f; aqd[i][j] = 0.f; akd[i][j] = 0.f; }

#pragma unroll 4
        for (int d = 0; d < 64; d++) {
            float qf[4], kf[4];
#pragma unroll
            for (int i = 0; i < 4; i++) qf[i] = q_s[(ty * 4 + i) * PAD + d];
#pragma unroll
            for (int j = 0; j < 4; j++) kf[j] = k_s[(tx * 4 + j) * PAD + d];
#pragma unroll
            for (int i = 0; i < 4; i++)
#pragma unroll
                for (int j = 0; j < 4; j++) {
                    float dbv = db_s[((ty * 4 + i) - (tx * 4 + j) + 63) * PAD + d];
                    aqk[i][j] += qf[i] * kf[j];
                    aqd[i][j] += qf[i] * dbv;
                    akd[i][j] += kf[j] * dbv;
                }
        }
        float mk[4];
#pragma unroll
        for (int j = 0; j < 4; j++) mk[j] = mask[b * L_ + kr0 + tx * 4 + j];
#pragma unroll
        for (int i = 0; i < 4; i++)
#pragma unroll
            for (int j = 0; j < 4; j++)
                s_s[(ty * 4 + i) * PAD + tx * 4 + j] =
                    (aqk[i][j] + aqd[i][j] + akd[i][j]) * 0.125f + mk[j];

        // --- 5 SSAN bias passes: (qw_i . k + ab) * struct_i ---
        for (int si = 0; si < 5; si++) {
            float a[4][4];
#pragma unroll
            for (int i = 0; i < 4; i++)
#pragma unroll
                for (int j = 0; j < 4; j++) a[i][j] = 0.f;
            const float* qwp = qw_s + si * 64 * PAD;
#pragma unroll 8
            for (int d = 0; d < 64; d++) {
                float qf[4], kf[4];
#pragma unroll
                for (int i = 0; i < 4; i++) qf[i] = qwp[(ty * 4 + i) * PAD + d];
#pragma unroll
                for (int j = 0; j < 4; j++) kf[j] = k_s[(tx * 4 + j) * PAD + d];
#pragma unroll
                for (int i = 0; i < 4; i++)
#pragma unroll
                    for (int j = 0; j < 4; j++) a[i][j] += qf[i] * kf[j];
            }
            const float ab = abs_bias[si * H_ + h];
            const float* stp = strm + ((size_t)(si * B_ + b) * L_ + ql0) * L_ + kr0;
#pragma unroll
            for (int i = 0; i < 4; i++) {
                float4 st4 = *(const float4*)&stp[(size_t)(ty * 4 + i) * L_ + tx * 4];
                float* srow = &s_s[(ty * 4 + i) * PAD + tx * 4];
                srow[0] += (a[i][0] + ab) * st4.x;
                srow[1] += (a[i][1] + ab) * st4.y;
                srow[2] += (a[i][2] + ab) * st4.z;
                srow[3] += (a[i][3] + ab) * st4.w;
            }
        }
        __syncthreads();

        // --- online softmax update (4 threads per row) ---
        {
            int row = tid >> 2, seg = tid & 3;
            float mloc = -__int_as_float(0x7f800000);
#pragma unroll
            for (int c = 0; c < 16; c++)
                mloc = fmaxf(mloc, s_s[row * PAD + seg * 16 + c]);
            mloc = fmaxf(mloc, __shfl_xor_sync(0xffffffffu, mloc, 1));
            mloc = fmaxf(mloc, __shfl_xor_sync(0xffffffffu, mloc, 2));
            float mold = row_m[row];
            float mnew = fmaxf(mold, mloc);
            float sl = 0.f;
#pragma unroll
            for (int c = 0; c < 16; c++) {
                float p = __expf(s_s[row * PAD + seg * 16 + c] - mnew);
                s_s[row * PAD + seg * 16 + c] = p;
                sl += p;
            }
            sl += __shfl_xor_sync(0xffffffffu, sl, 1);
            sl += __shfl_xor_sync(0xffffffffu, sl, 2);
            if (seg == 0) {
                float f = __expf(mold - mnew);
                row_f[row] = f;
                row_m[row] = mnew;
                row_s[row] = row_s[row] * f + sl;
            }
        }
        __syncthreads();

        // --- rescale + P@V ---
        float fr[4];
#pragma unroll
        for (int i = 0; i < 4; i++) fr[i] = row_f[ty * 4 + i];
#pragma unroll
        for (int i = 0; i < 4; i++)
#pragma unroll
            for (int j = 0; j < 4; j++) o[i][j] *= fr[i];

#pragma unroll 8
        for (int r = 0; r < 64; r++) {
            float pf[4], vf[4];
#pragma unroll
            for (int i = 0; i < 4; i++) pf[i] = s_s[(ty * 4 + i) * PAD + r];
#pragma unroll
            for (int j = 0; j < 4; j++) vf[j] = v_s[r * PAD + tx * 4 + j];
#pragma unroll
            for (int i = 0; i < 4; i++)
#pragma unroll
                for (int j = 0; j < 4; j++) o[i][j] += pf[i] * vf[j];
        }
        __syncthreads();
    }

    // epilogue: divide by row sums, write [b, l, h*64+e]
#pragma unroll
    for (int i = 0; i < 4; i++) {
        int l = ql0 + ty * 4 + i;
        float inv = 1.f / row_s[ty * 4 + i];
        float4 w4;
        w4.x = o[i][0] * inv;
        w4.y = o[i][1] * inv;
        w4.z = o[i][2] * inv;
        w4.w = o[i][3] * inv;
        *(float4*)&out[((size_t)(b * L_ + l)) * D_ + h * DH_ + tx * 4] = w4;
    }
}

// ---------------------------------------------------------------------------
extern "C" void kernel_launch(void* const* d_in, const int* in_sizes, int n_in,
                              void* d_out, int out_size)
{
    const float* X    = (const float*)d_in[0];
    const float* mask = (const float*)d_in[1];
    const float* strm = (const float*)d_in[2];
    const float* Wq   = (const float*)d_in[3];
    const float* bq   = (const float*)d_in[4];
    const float* Wk   = (const float*)d_in[5];
    const float* bk   = (const float*)d_in[6];
    const float* Wv   = (const float*)d_in[7];
    const float* bv   = (const float*)d_in[8];
    const float* dist = (const float*)d_in[9];
    const float* ssan = (const float*)d_in[10];
    const float* ab   = (const float*)d_in[11];
    float* out = (float*)d_out;

    qkv_proj_kernel<<<dim3(6, 16, 3), 256>>>(X, Wq, bq, Wk, bk, Wv, bv);
    qw_proj_kernel<<<dim3(32, 12, 5), 256>>>(ssan);

    const int smem_bytes = SMEM_FLOATS * (int)sizeof(float);
    cudaFuncSetAttribute(attn_kernel, cudaFuncAttributeMaxDynamicSharedMemorySize, smem_bytes);
    attn_kernel<<<dim3(16, 12, 2), 256, smem_bytes>>>(mask, strm, dist, ab, out);
}

// round 3
// speedup vs baseline: 1.0070x; 1.0070x over previous
#include <cuda_runtime.h>

#define B_ 2
#define L_ 1024
#define D_ 768
#define H_ 12
#define DH_ 64
#define NS_ 5
#define PAD 65

// Scratch (static device arrays: allocation-free per harness rules)
__device__ float g_Q[B_*H_*L_*DH_];
__device__ float g_K[B_*H_*L_*DH_];
__device__ float g_V[B_*H_*L_*DH_];
__device__ float g_QW[NS_*B_*H_*L_*DH_];

// ---------------------------------------------------------------------------
// Kernel 1: QKV projections.  X[2048,768] @ W[768,768] + b, output in
// head-major layout  g_{Q,K,V}[b][h][l][d].
// 128x128x8 tile, 256 threads, 8x8 register tiles.
// ---------------------------------------------------------------------------
__global__ __launch_bounds__(256) void qkv_proj_kernel(
    const float* __restrict__ X,
    const float* __restrict__ Wq, const float* __restrict__ bq,
    const float* __restrict__ Wk, const float* __restrict__ bk,
    const float* __restrict__ Wv, const float* __restrict__ bv)
{
    __shared__ float a_s[8][132];   // [k][m], padded
    __shared__ float b_s[8][128];   // [k][n]

    const int z = blockIdx.z;
    const float* W    = (z == 0) ? Wq : ((z == 1) ? Wk : Wv);
    const float* bias = (z == 0) ? bq : ((z == 1) ? bk : bv);
    float* dst        = (z == 0) ? g_Q : ((z == 1) ? g_K : g_V);

    const int tid = threadIdx.x;
    const int tx = tid & 15, ty = tid >> 4;
    const int m0 = blockIdx.y * 128, n0 = blockIdx.x * 128;

    const int arow = tid >> 1;          // 0..127
    const int acol = (tid & 1) * 4;     // 0 or 4
    const int brow = tid >> 5;          // 0..7
    const int bcol = (tid & 31) * 4;    // 0..124

    float acc[8][8];
#pragma unroll
    for (int i = 0; i < 8; i++)
#pragma unroll
        for (int j = 0; j < 8; j++) acc[i][j] = 0.f;

    for (int kt = 0; kt < D_; kt += 8) {
        float4 av  = *(const float4*)&X[(m0 + arow) * D_ + kt + acol];
        float4 bvv = *(const float4*)&W[(kt + brow) * D_ + n0 + bcol];
        __syncthreads();
        a_s[acol + 0][arow] = av.x;
        a_s[acol + 1][arow] = av.y;
        a_s[acol + 2][arow] = av.z;
        a_s[acol + 3][arow] = av.w;
        *(float4*)&b_s[brow][bcol] = bvv;
        __syncthreads();
#pragma unroll
        for (int kk = 0; kk < 8; kk++) {
            float af[8], bf[8];
#pragma unroll
            for (int i = 0; i < 8; i++) af[i] = a_s[kk][ty * 8 + i];
#pragma unroll
            for (int j = 0; j < 8; j++) bf[j] = b_s[kk][tx * 8 + j];
#pragma unroll
            for (int i = 0; i < 8; i++)
#pragma unroll
                for (int j = 0; j < 8; j++) acc[i][j] += af[i] * bf[j];
        }
    }

#pragma unroll
    for (int i = 0; i < 8; i++) {
        int mg = m0 + ty * 8 + i;
        int bb = mg >> 10, l = mg & 1023;
#pragma unroll
        for (int j = 0; j < 8; j++) {
            int ng = n0 + tx * 8 + j;
            int h = ng >> 6, e = ng & 63;
            dst[((bb * H_ + h) * L_ + l) * DH_ + e] = acc[i][j] + bias[ng];
        }
    }
}

// ---------------------------------------------------------------------------
// Kernel 2: qw_i[b,h,l,e] = sum_d q[b,h,l,d] * ssan_w[i,h,d,e]
// grid (rowtile 32, h 12, i 5), 256 threads, 4x4 register tiles.
// ---------------------------------------------------------------------------
__global__ __launch_bounds__(256) void qw_proj_kernel(const float* __restrict__ ssan_w)
{
    __shared__ float q_s[64][PAD];
    __shared__ float w_s[64][PAD];  // w_s[d][e]

    const int si = blockIdx.z, h = blockIdx.y, bt = blockIdx.x;
    const int tid = threadIdx.x;
    const int tx = tid & 15, ty = tid >> 4;

    for (int idx = tid; idx < 64 * 64; idx += 256) {
        int r = idx >> 6, d = idx & 63;
        int gr = bt * 64 + r;
        int bb = gr >> 10, l = gr & 1023;
        q_s[r][d] = g_Q[((bb * H_ + h) * L_ + l) * DH_ + d];
        w_s[r][d] = ssan_w[((si * H_ + h) * DH_ + r) * DH_ + d];
    }
    __syncthreads();

    float acc[4][4];
#pragma unroll
    for (int i = 0; i < 4; i++)
#pragma unroll
        for (int j = 0; j < 4; j++) acc[i][j] = 0.f;

#pragma unroll 8
    for (int dd = 0; dd < 64; dd++) {
        float qf[4], wf[4];
#pragma unroll
        for (int i = 0; i < 4; i++) qf[i] = q_s[ty * 4 + i][dd];
#pragma unroll
        for (int j = 0; j < 4; j++) wf[j] = w_s[dd][tx * 4 + j];
#pragma unroll
        for (int i = 0; i < 4; i++)
#pragma unroll
            for (int j = 0; j < 4; j++) acc[i][j] += qf[i] * wf[j];
    }

#pragma unroll
    for (int i = 0; i < 4; i++) {
        int gr = bt * 64 + ty * 4 + i;
        int bb = gr >> 10, l = gr & 1023;
#pragma unroll
        for (int j = 0; j < 4; j++) {
            int e = tx * 4 + j;
            g_QW[(((si * B_ + bb) * H_ + h) * L_ + l) * DH_ + e] = acc[i][j];
        }
    }
}

// ---------------------------------------------------------------------------
// Kernel 3: fused flash-style attention with relative-position band and
// 5 struct-masked SSAN bias GEMMs. One CTA per (b, h, 64-row q-tile).
// 256 threads (16x16), 4x4 register tiles per phase.
// ---------------------------------------------------------------------------
// smem layout (floats):
#define OFF_Q   0
#define OFF_QW  (64 * PAD)
#define OFF_K   (OFF_QW + 5 * 64 * PAD)
#define OFF_V   (OFF_K + 64 * PAD)
#define OFF_DB  (OFF_V + 64 * PAD)
#define OFF_S   (OFF_DB + 127 * PAD)
#define OFF_RM  (OFF_S + 64 * PAD)
#define OFF_RS  (OFF_RM + 64)
#define OFF_RF  (OFF_RS + 64)
#define SMEM_FLOATS (OFF_RF + 64)

__global__ __launch_bounds__(256) void attn_kernel(
    const float* __restrict__ mask,       // [B,1,1,L]
    const float* __restrict__ strm,       // [5,B,1,L,L]
    const float* __restrict__ dist,       // [2047, 64]
    const float* __restrict__ abs_bias,   // [5, H]
    float* __restrict__ out)              // [B, L, 768]
{
    extern __shared__ float sm[];
    float* q_s  = sm + OFF_Q;
    float* qw_s = sm + OFF_QW;
    float* k_s  = sm + OFF_K;
    float* v_s  = sm + OFF_V;
    float* db_s = sm + OFF_DB;
    float* s_s  = sm + OFF_S;
    float* row_m = sm + OFF_RM;
    float* row_s = sm + OFF_RS;
    float* row_f = sm + OFF_RF;

    const int qt = blockIdx.x, h = blockIdx.y, b = blockIdx.z;
    const int tid = threadIdx.x;
    const int tx = tid & 15, ty = tid >> 4;
    const int ql0 = qt * 64;
    const int bh = b * H_ + h;

    // load q tile + 5 qw tiles (persistent)
    for (int idx = tid; idx < 64 * 64; idx += 256) {
        int l = idx >> 6, d = idx & 63;
        q_s[l * PAD + d] = g_Q[(bh * L_ + ql0 + l) * DH_ + d];
    }
    for (int idx = tid; idx < 5 * 64 * 64; idx += 256) {
        int si = idx >> 12;
        int rem = idx & 4095;
        int l = rem >> 6, d = rem & 63;
        qw_s[(si * 64 + l) * PAD + d] =
            g_QW[si * (B_ * H_ * L_ * DH_) + (bh * L_ + ql0 + l) * DH_ + d];
    }
    if (tid < 64) {
        row_m[tid] = -__int_as_float(0x7f800000);  // -inf
        row_s[tid] = 0.f;
    }

    float o[4][4];
#pragma unroll
    for (int i = 0; i < 4; i++)
#pragma unroll
        for (int j = 0; j < 4; j++) o[i][j] = 0.f;

    __syncthreads();

    for (int kt = 0; kt < 16; kt++) {
        const int kr0 = kt * 64;
        // stage k, v tiles
        for (int idx = tid; idx < 64 * 64; idx += 256) {
            int r = idx >> 6, d = idx & 63;
            k_s[r * PAD + d] = g_K[(bh * L_ + kr0 + r) * DH_ + d];
            v_s[r * PAD + d] = g_V[(bh * L_ + kr0 + r) * DH_ + d];
        }
        // stage dist band: m = l - r + 1023 = m0 + (li - ri + 63)
        const int m0 = ql0 - kr0 + 960;
        for (int idx = tid; idx < 127 * 64; idx += 256) {
            int j = idx >> 6, d = idx & 63;
            db_s[j * PAD + d] = dist[(m0 + j) * DH_ + d];
        }
        __syncthreads();

        // --- pass A: q.k + q.dist + k.dist ---
        float aqk[4][4], aqd[4][4], akd[4][4];
#pragma unroll
        for (int i = 0; i < 4; i++)
#pragma unroll
            for (int j = 0; j < 4; j++) { aqk[i][j] = 0.f; aqd[i][j] = 0.f; akd[i][j] = 0.f; }

#pragma unroll 4
        for (int d = 0; d < 64; d++) {
            float qf[4], kf[4];
#pragma unroll
            for (int i = 0; i < 4; i++) qf[i] = q_s[(ty * 4 + i) * PAD + d];
#pragma unroll
            for (int j = 0; j < 4; j++) kf[j] = k_s[(tx * 4 + j) * PAD + d];
#pragma unroll
            for (int i = 0; i < 4; i++)
#pragma unroll
                for (int j = 0; j < 4; j++) {
                    float dbv = db_s[((ty * 4 + i) - (tx * 4 + j) + 63) * PAD + d];
                    aqk[i][j] += qf[i] * kf[j];
                    aqd[i][j] += qf[i] * dbv;
                    akd[i][j] += kf[j] * dbv;
                }
        }
        float mk[4];
#pragma unroll
        for (int j = 0; j < 4; j++) mk[j] = mask[b * L_ + kr0 + tx * 4 + j];
#pragma unroll
        for (int i = 0; i < 4; i++)
#pragma unroll
            for (int j = 0; j < 4; j++)
                s_s[(ty * 4 + i) * PAD + tx * 4 + j] =
                    (aqk[i][j] + aqd[i][j] + akd[i][j]) * 0.125f + mk[j];

        // --- 5 SSAN bias passes: (qw_i . k + ab) * struct_i ---
        for (int si = 0; si < 5; si++) {
            float a[4][4];
#pragma unroll
            for (int i = 0; i < 4; i++)
#pragma unroll
                for (int j = 0; j < 4; j++) a[i][j] = 0.f;
            const float* qwp = qw_s + si * 64 * PAD;
#pragma unroll 8
            for (int d = 0; d < 64; d++) {
                float qf[4], kf[4];
#pragma unroll
                for (int i = 0; i < 4; i++) qf[i] = qwp[(ty * 4 + i) * PAD + d];
#pragma unroll
                for (int j = 0; j < 4; j++) kf[j] = k_s[(tx * 4 + j) * PAD + d];
#pragma unroll
                for (int i = 0; i < 4; i++)
#pragma unroll
                    for (int j = 0; j < 4; j++) a[i][j] += qf[i] * kf[j];
            }
            const float ab = abs_bias[si * H_ + h];
            const float* stp = strm + ((size_t)(si * B_ + b) * L_ + ql0) * L_ + kr0;
#pragma unroll
            for (int i = 0; i < 4; i++) {
                float4 st4 = *(const float4*)&stp[(size_t)(ty * 4 + i) * L_ + tx * 4];
                float* srow = &s_s[(ty * 4 + i) * PAD + tx * 4];
                srow[0] += (a[i][0] + ab) * st4.x;
                srow[1] += (a[i][1] + ab) * st4.y;
                srow[2] += (a[i][2] + ab) * st4.z;
                srow[3] += (a[i][3] + ab) * st4.w;
            }
        }
        __syncthreads();

        // --- online softmax update (4 threads per row) ---
        {
            int row = tid >> 2, seg = tid & 3;
            float mloc = -__int_as_float(0x7f800000);
#pragma unroll
            for (int c = 0; c < 16; c++)
                mloc = fmaxf(mloc, s_s[row * PAD + seg * 16 + c]);
            mloc = fmaxf(mloc, __shfl_xor_sync(0xffffffffu, mloc, 1));
            mloc = fmaxf(mloc, __shfl_xor_sync(0xffffffffu, mloc, 2));
            float mold = row_m[row];
            float mnew = fmaxf(mold, mloc);
            float sl = 0.f;
#pragma unroll
            for (int c = 0; c < 16; c++) {
                float p = __expf(s_s[row * PAD + seg * 16 + c] - mnew);
                s_s[row * PAD + seg * 16 + c] = p;
                sl += p;
            }
            sl += __shfl_xor_sync(0xffffffffu, sl, 1);
            sl += __shfl_xor_sync(0xffffffffu, sl, 2);
            if (seg == 0) {
                float f = __expf(mold - mnew);
                row_f[row] = f;
                row_m[row] = mnew;
                row_s[row] = row_s[row] * f + sl;
            }
        }
        __syncthreads();

        // --- rescale + P@V ---
        float fr[4];
#pragma unroll
        for (int i = 0; i < 4; i++) fr[i] = row_f[ty * 4 + i];
#pragma unroll
        for (int i = 0; i < 4; i++)
#pragma unroll
            for (int j = 0; j < 4; j++) o[i][j] *= fr[i];

#pragma unroll 8
        for (int r = 0; r < 64; r++) {
            float pf[4], vf[4];
#pragma unroll
            for (int i = 0; i < 4; i++) pf[i] = s_s[(ty * 4 + i) * PAD + r];
#pragma unroll
            for (int j = 0; j < 4; j++) vf[j] = v_s[r * PAD + tx * 4 + j];
#pragma unroll
            for (int i = 0; i < 4; i++)
#pragma unroll
                for (int j = 0; j < 4; j++) o[i][j] += pf[i] * vf[j];
        }
        __syncthreads();
    }

    // epilogue: divide by row sums, write [b, l, h*64+e]
#pragma unroll
    for (int i = 0; i < 4; i++) {
        int l = ql0 + ty * 4 + i;
        float inv = 1.f / row_s[ty * 4 + i];
        float4 w4;
        w4.x = o[i][0] * inv;
        w4.y = o[i][1] * inv;
        w4.z = o[i][2] * inv;
        w4.w = o[i][3] * inv;
        *(float4*)&out[((size_t)(b * L_ + l)) * D_ + h * DH_ + tx * 4] = w4;
    }
}

// ---------------------------------------------------------------------------
extern "C" void kernel_launch(void* const* d_in, const int* in_sizes, int n_in,
                              void* d_out, int out_size)
{
    const float* X    = (const float*)d_in[0];
    const float* mask = (const float*)d_in[1];
    const float* strm = (const float*)d_in[2];
    const float* Wq   = (const float*)d_in[3];
    const float* bq   = (const float*)d_in[4];
    const float* Wk   = (const float*)d_in[5];
    const float* bk   = (const float*)d_in[6];
    const float* Wv   = (const float*)d_in[7];
    const float* bv   = (const float*)d_in[8];
    const float* dist = (const float*)d_in[9];
    const float* ssan = (const float*)d_in[10];
    const float* ab   = (const float*)d_in[11];
    float* out = (float*)d_out;

    qkv_proj_kernel<<<dim3(6, 16, 3), 256>>>(X, Wq, bq, Wk, bk, Wv, bv);
    qw_proj_kernel<<<dim3(32, 12, 5), 256>>>(ssan);

    const int smem_bytes = SMEM_FLOATS * (int)sizeof(float);
    cudaFuncSetAttribute(attn_kernel, cudaFuncAttributeMaxDynamicSharedMemorySize, smem_bytes);
    attn_kernel<<<dim3(16, 12, 2), 256, smem_bytes>>>(mask, strm, dist, ab, out);
}

// round 5
// speedup vs baseline: 1.4912x; 1.4808x over previous
#include <cuda_runtime.h>

#define B_ 2
#define L_ 1024
#define D_ 768
#define H_ 12
#define DH_ 64
#define NS_ 5
#define PAD 65

// Scratch (static device arrays: allocation-free per harness rules)
__device__ float g_Q[B_*H_*L_*DH_];
__device__ float g_K[B_*H_*L_*DH_];
__device__ float g_V[B_*H_*L_*DH_];
__device__ float g_QW[NS_*B_*H_*L_*DH_];

// ---------------------------------------------------------------------------
// Kernel 1: QKV projections (fp32, at FMA roofline — tensorize next round)
// ---------------------------------------------------------------------------
__global__ __launch_bounds__(256) void qkv_proj_kernel(
    const float* __restrict__ X,
    const float* __restrict__ Wq, const float* __restrict__ bq,
    const float* __restrict__ Wk, const float* __restrict__ bk,
    const float* __restrict__ Wv, const float* __restrict__ bv)
{
    __shared__ float a_s[8][132];
    __shared__ float b_s[8][128];

    const int z = blockIdx.z;
    const float* W    = (z == 0) ? Wq : ((z == 1) ? Wk : Wv);
    const float* bias = (z == 0) ? bq : ((z == 1) ? bk : bv);
    float* dst        = (z == 0) ? g_Q : ((z == 1) ? g_K : g_V);

    const int tid = threadIdx.x;
    const int tx = tid & 15, ty = tid >> 4;
    const int m0 = blockIdx.y * 128, n0 = blockIdx.x * 128;

    const int arow = tid >> 1;
    const int acol = (tid & 1) * 4;
    const int brow = tid >> 5;
    const int bcol = (tid & 31) * 4;

    float acc[8][8];
#pragma unroll
    for (int i = 0; i < 8; i++)
#pragma unroll
        for (int j = 0; j < 8; j++) acc[i][j] = 0.f;

    for (int kt = 0; kt < D_; kt += 8) {
        float4 av  = *(const float4*)&X[(m0 + arow) * D_ + kt + acol];
        float4 bvv = *(const float4*)&W[(kt + brow) * D_ + n0 + bcol];
        __syncthreads();
        a_s[acol + 0][arow] = av.x;
        a_s[acol + 1][arow] = av.y;
        a_s[acol + 2][arow] = av.z;
        a_s[acol + 3][arow] = av.w;
        *(float4*)&b_s[brow][bcol] = bvv;
        __syncthreads();
#pragma unroll
        for (int kk = 0; kk < 8; kk++) {
            float af[8], bf[8];
#pragma unroll
            for (int i = 0; i < 8; i++) af[i] = a_s[kk][ty * 8 + i];
#pragma unroll
            for (int j = 0; j < 8; j++) bf[j] = b_s[kk][tx * 8 + j];
#pragma unroll
            for (int i = 0; i < 8; i++)
#pragma unroll
                for (int j = 0; j < 8; j++) acc[i][j] += af[i] * bf[j];
        }
    }

#pragma unroll
    for (int i = 0; i < 8; i++) {
        int mg = m0 + ty * 8 + i;
        int bb = mg >> 10, l = mg & 1023;
#pragma unroll
        for (int j = 0; j < 8; j++) {
            int ng = n0 + tx * 8 + j;
            int h = ng >> 6, e = ng & 63;
            dst[((bb * H_ + h) * L_ + l) * DH_ + e] = acc[i][j] + bias[ng];
        }
    }
}

// ---------------------------------------------------------------------------
// Kernel 2: qw projections (fp32, unchanged)
// ---------------------------------------------------------------------------
__global__ __launch_bounds__(256) void qw_proj_kernel(const float* __restrict__ ssan_w)
{
    __shared__ float q_s[64][PAD];
    __shared__ float w_s[64][PAD];

    const int si = blockIdx.z, h = blockIdx.y, bt = blockIdx.x;
    const int tid = threadIdx.x;
    const int tx = tid & 15, ty = tid >> 4;

    for (int idx = tid; idx < 64 * 64; idx += 256) {
        int r = idx >> 6, d = idx & 63;
        int gr = bt * 64 + r;
        int bb = gr >> 10, l = gr & 1023;
        q_s[r][d] = g_Q[((bb * H_ + h) * L_ + l) * DH_ + d];
        w_s[r][d] = ssan_w[((si * H_ + h) * DH_ + r) * DH_ + d];
    }
    __syncthreads();

    float acc[4][4];
#pragma unroll
    for (int i = 0; i < 4; i++)
#pragma unroll
        for (int j = 0; j < 4; j++) acc[i][j] = 0.f;

#pragma unroll 8
    for (int dd = 0; dd < 64; dd++) {
        float qf[4], wf[4];
#pragma unroll
        for (int i = 0; i < 4; i++) qf[i] = q_s[ty * 4 + i][dd];
#pragma unroll
        for (int j = 0; j < 4; j++) wf[j] = w_s[dd][tx * 4 + j];
#pragma unroll
        for (int i = 0; i < 4; i++)
#pragma unroll
            for (int j = 0; j < 4; j++) acc[i][j] += qf[i] * wf[j];
    }

#pragma unroll
    for (int i = 0; i < 4; i++) {
        int gr = bt * 64 + ty * 4 + i;
        int bb = gr >> 10, l = gr & 1023;
#pragma unroll
        for (int j = 0; j < 4; j++) {
            int e = tx * 4 + j;
            g_QW[(((si * B_ + bb) * H_ + h) * L_ + l) * DH_ + e] = acc[i][j];
        }
    }
}

// ---------------------------------------------------------------------------
// Kernel 3: tf32 mma.sync fused attention with split-tf32 error compensation.
// One CTA per (b, h, 64-row q-tile); 256 threads = 8 warps.
// ---------------------------------------------------------------------------
#define ST  68      // row stride for 64-col tiles
#define VST 72      // V tile stride (conflict-free B-frag loads)
#define GST 132     // band-GEMM result stride (128 cols)

// region A: band result buffer GB (64*132=8448) ALIASED with Ph/Pl (2*4352)
#define OFF_GB 0
#define OFF_PH 0
#define OFF_PL (OFF_PH + 64*ST)
#define REG_A  (2 * 64 * ST)            // 8704 >= 8448
#define OFF_QW (REG_A)                  // 5*64*68 = 21760
#define OFF_KH (OFF_QW + 5*64*ST)
#define OFF_KL (OFF_KH + 64*ST)
#define OFF_VH (OFF_KL + 64*ST)
#define OFF_VL (OFF_VH + 64*VST)
#define OFF_DB (OFF_VL + 64*VST)        // 128*68
#define OFF_PM (OFF_DB + 128*ST)        // partial max [2][64]
#define OFF_PS (OFF_PM + 128)           // partial sum [2][64]
#define OFF_RM (OFF_PS + 128)           // running max [64]
#define OFF_RS (OFF_RM + 64)            // running sum [64]
#define OFF_MB (OFF_RS + 64)            // mnew broadcast [64]
#define OFF_FB (OFF_MB + 64)            // rescale factor broadcast [64]
#define SMEMF  (OFF_FB + 64)            // 57600 floats = 230400 B

__device__ __forceinline__ void mma_tf32(float* d, const unsigned* a, const unsigned* b)
{
    asm volatile(
        "mma.sync.aligned.m16n8k8.row.col.f32.tf32.tf32.f32 "
        "{%0,%1,%2,%3}, {%4,%5,%6,%7}, {%8,%9}, {%0,%1,%2,%3};\n"
        : "+f"(d[0]), "+f"(d[1]), "+f"(d[2]), "+f"(d[3])
        : "r"(a[0]), "r"(a[1]), "r"(a[2]), "r"(a[3]), "r"(b[0]), "r"(b[1]));
}

__device__ __forceinline__ unsigned tf32u(float x)
{
    unsigned r;
    asm("cvt.rna.tf32.f32 %0, %1;" : "=r"(r) : "f"(x));
    return r;
}
__device__ __forceinline__ float tf32f(float x) { return __uint_as_float(tf32u(x)); }

__global__ __launch_bounds__(256) void attn_mma_kernel(
    const float* __restrict__ mask,       // [B,1,1,L]
    const float* __restrict__ strm,       // [5,B,1,L,L]
    const float* __restrict__ dist,       // [2047, 64]
    const float* __restrict__ abs_bias,   // [5, H]
    float* __restrict__ out)              // [B, L, 768]
{
    extern __shared__ float sm[];

    const int tid  = threadIdx.x;
    const int lane = tid & 31, w = tid >> 5;
    const int wy = w >> 1, wx = w & 1;
    const int gid = lane >> 2, tig = lane & 3;

    const int qt = blockIdx.x, h = blockIdx.y, b = blockIdx.z;
    const int ql0 = qt * 64;
    const int bh = b * H_ + h;

    const int r0 = wy * 16 + gid;
    const int r1 = r0 + 8;

    // ---- prologue: stage Q (temporarily in region A) and QW ----
    for (int idx = tid; idx < 64 * 16; idx += 256) {
        int r = idx >> 4, c4 = (idx & 15) << 2;
        *(float4*)&sm[OFF_GB + r * ST + c4] =
            *(const float4*)&g_Q[(bh * L_ + ql0 + r) * DH_ + c4];
    }
    for (int idx = tid; idx < 5 * 64 * 16; idx += 256) {
        int si = idx >> 10, rem = idx & 1023;
        int r = rem >> 4, c4 = (rem & 15) << 2;
        *(float4*)&sm[OFF_QW + si * (64 * ST) + r * ST + c4] =
            *(const float4*)&g_QW[(size_t)si * (B_ * H_ * L_ * DH_) +
                                  (bh * L_ + ql0 + r) * DH_ + c4];
    }
    if (tid < 64) { sm[OFF_RM + tid] = -1e30f; sm[OFF_RS + tid] = 0.f; }
    __syncthreads();

    // persistent Q A-fragments (RNA-rounded tf32; single precision for QK)
    unsigned qa[8][4];
#pragma unroll
    for (int ks = 0; ks < 8; ks++) {
        int a0 = OFF_GB + r0 * ST + ks * 8 + tig;
        qa[ks][0] = tf32u(sm[a0]);
        qa[ks][1] = tf32u(sm[a0 + 8 * ST]);
        qa[ks][2] = tf32u(sm[a0 + 4]);
        qa[ks][3] = tf32u(sm[a0 + 8 * ST + 4]);
    }
    float ab[5];
#pragma unroll
    for (int si = 0; si < 5; si++) ab[si] = abs_bias[si * H_ + h];

    float o[4][4];
#pragma unroll
    for (int nf = 0; nf < 4; nf++)
#pragma unroll
        for (int e = 0; e < 4; e++) o[nf][e] = 0.f;

    for (int kt = 0; kt < 16; kt++) {
        const int kr0 = kt * 64;
        __syncthreads();  // region A free (prev PV done / prologue done)

        // ---- stage K hi/lo, V hi/lo, DB (all RNA tf32) ----
        for (int idx = tid; idx < 1024; idx += 256) {
            int r = idx >> 4, c4 = (idx & 15) << 2;
            float4 kv = *(const float4*)&g_K[(bh * L_ + kr0 + r) * DH_ + c4];
            float4 kh, kl;
            kh.x = tf32f(kv.x); kl.x = tf32f(kv.x - kh.x);
            kh.y = tf32f(kv.y); kl.y = tf32f(kv.y - kh.y);
            kh.z = tf32f(kv.z); kl.z = tf32f(kv.z - kh.z);
            kh.w = tf32f(kv.w); kl.w = tf32f(kv.w - kh.w);
            *(float4*)&sm[OFF_KH + r * ST + c4] = kh;
            *(float4*)&sm[OFF_KL + r * ST + c4] = kl;

            float4 vv = *(const float4*)&g_V[(bh * L_ + kr0 + r) * DH_ + c4];
            float4 vh, vl;
            vh.x = tf32f(vv.x); vl.x = tf32f(vv.x - vh.x);
            vh.y = tf32f(vv.y); vl.y = tf32f(vv.y - vh.y);
            vh.z = tf32f(vv.z); vl.z = tf32f(vv.z - vh.z);
            vh.w = tf32f(vv.w); vl.w = tf32f(vv.w - vh.w);
            *(float4*)&sm[OFF_VH + r * VST + c4] = vh;
            *(float4*)&sm[OFF_VL + r * VST + c4] = vl;
        }
        const int m0 = ql0 - kr0 + 960;
        for (int idx = tid; idx < 2048; idx += 256) {
            int r = idx >> 4, c4 = (idx & 15) << 2;
            float4 dv = make_float4(0.f, 0.f, 0.f, 0.f);
            if (r < 127) {
                dv = *(const float4*)&dist[(m0 + r) * DH_ + c4];
                dv.x = tf32f(dv.x); dv.y = tf32f(dv.y);
                dv.z = tf32f(dv.z); dv.w = tf32f(dv.w);
            }
            *(float4*)&sm[OFF_DB + r * ST + c4] = dv;
        }
        __syncthreads();

        float sacc[4][4];
#pragma unroll
        for (int nf = 0; nf < 4; nf++)
#pragma unroll
            for (int e = 0; e < 4; e++) sacc[nf][e] = 0.f;

        // ---- Gq = Q @ DB^T (64x128) -> GB ----
        {
            float gg[8][4];
#pragma unroll
            for (int nf = 0; nf < 8; nf++)
#pragma unroll
                for (int e = 0; e < 4; e++) gg[nf][e] = 0.f;
#pragma unroll
            for (int ks = 0; ks < 8; ks++)
#pragma unroll
                for (int nf = 0; nf < 8; nf++) {
                    unsigned bb[2];
                    int na = OFF_DB + (wx * 64 + nf * 8 + gid) * ST + ks * 8 + tig;
                    bb[0] = __float_as_uint(sm[na]);
                    bb[1] = __float_as_uint(sm[na + 4]);
                    mma_tf32(gg[nf], qa[ks], bb);
                }
#pragma unroll
            for (int nf = 0; nf < 8; nf++) {
                int c0 = wx * 64 + nf * 8 + 2 * tig;
                *(float2*)&sm[OFF_GB + r0 * GST + c0] = make_float2(gg[nf][0], gg[nf][1]);
                *(float2*)&sm[OFF_GB + r1 * GST + c0] = make_float2(gg[nf][2], gg[nf][3]);
            }
        }
        __syncthreads();

        // gather Gq diagonals: S[i][j] += Gq[i][i-j+63]
#pragma unroll
        for (int nf = 0; nf < 4; nf++) {
            int c0 = wx * 32 + nf * 8 + 2 * tig;
            sacc[nf][0] += sm[OFF_GB + r0 * GST + (r0 - c0 + 63)];
            sacc[nf][1] += sm[OFF_GB + r0 * GST + (r0 - c0 + 62)];
            sacc[nf][2] += sm[OFF_GB + r1 * GST + (r1 - c0 + 63)];
            sacc[nf][3] += sm[OFF_GB + r1 * GST + (r1 - c0 + 62)];
        }
        __syncthreads();

        // ---- Gk = K @ DB^T (64x128) -> GB ----
        {
            float gg[8][4];
#pragma unroll
            for (int nf = 0; nf < 8; nf++)
#pragma unroll
                for (int e = 0; e < 4; e++) gg[nf][e] = 0.f;
#pragma unroll
            for (int ks = 0; ks < 8; ks++) {
                unsigned ka[4];
                int aa = OFF_KH + r0 * ST + ks * 8 + tig;
                ka[0] = __float_as_uint(sm[aa]);
                ka[1] = __float_as_uint(sm[aa + 8 * ST]);
                ka[2] = __float_as_uint(sm[aa + 4]);
                ka[3] = __float_as_uint(sm[aa + 8 * ST + 4]);
#pragma unroll
                for (int nf = 0; nf < 8; nf++) {
                    unsigned bb[2];
                    int na = OFF_DB + (wx * 64 + nf * 8 + gid) * ST + ks * 8 + tig;
                    bb[0] = __float_as_uint(sm[na]);
                    bb[1] = __float_as_uint(sm[na + 4]);
                    mma_tf32(gg[nf], ka, bb);
                }
            }
#pragma unroll
            for (int nf = 0; nf < 8; nf++) {
                int c0 = wx * 64 + nf * 8 + 2 * tig;
                *(float2*)&sm[OFF_GB + r0 * GST + c0] = make_float2(gg[nf][0], gg[nf][1]);
                *(float2*)&sm[OFF_GB + r1 * GST + c0] = make_float2(gg[nf][2], gg[nf][3]);
            }
        }
        __syncthreads();

        // gather Gk diagonals: S[i][j] += Gk[j][i-j+63]
#pragma unroll
        for (int nf = 0; nf < 4; nf++) {
            int c0 = wx * 32 + nf * 8 + 2 * tig;
            sacc[nf][0] += sm[OFF_GB + c0 * GST + (r0 - c0 + 63)];
            sacc[nf][1] += sm[OFF_GB + (c0 + 1) * GST + (r0 - c0 + 62)];
            sacc[nf][2] += sm[OFF_GB + c0 * GST + (r1 - c0 + 63)];
            sacc[nf][3] += sm[OFF_GB + (c0 + 1) * GST + (r1 - c0 + 62)];
        }

        // ---- fused QK + 5 SSAN GEMMs (split-tf32), ks outer ----
        float bacc[5][4][4];
#pragma unroll
        for (int si = 0; si < 5; si++)
#pragma unroll
            for (int nf = 0; nf < 4; nf++)
#pragma unroll
                for (int e = 0; e < 4; e++) bacc[si][nf][e] = 0.f;

#pragma unroll
        for (int ks = 0; ks < 8; ks++) {
            unsigned bkh[4][2], bkl[4][2];
#pragma unroll
            for (int nf = 0; nf < 4; nf++) {
                int na = OFF_KH + (wx * 32 + nf * 8 + gid) * ST + ks * 8 + tig;
                bkh[nf][0] = __float_as_uint(sm[na]);
                bkh[nf][1] = __float_as_uint(sm[na + 4]);
                int nl = na + (OFF_KL - OFF_KH);
                bkl[nf][0] = __float_as_uint(sm[nl]);
                bkl[nf][1] = __float_as_uint(sm[nl + 4]);
            }
            // QK: q_tf32 * (Kh + Kl)
#pragma unroll
            for (int nf = 0; nf < 4; nf++) {
                mma_tf32(sacc[nf], qa[ks], bkh[nf]);
                mma_tf32(sacc[nf], qa[ks], bkl[nf]);
            }
            // SSAN: (QWh + QWl) * Kh + QWh * Kl
#pragma unroll
            for (int si = 0; si < 5; si++) {
                int aa = OFF_QW + si * (64 * ST) + r0 * ST + ks * 8 + tig;
                float w0 = sm[aa], w1 = sm[aa + 8 * ST];
                float w2 = sm[aa + 4], w3 = sm[aa + 8 * ST + 4];
                unsigned wah[4], wal[4];
                wah[0] = tf32u(w0); wal[0] = tf32u(w0 - __uint_as_float(wah[0]));
                wah[1] = tf32u(w1); wal[1] = tf32u(w1 - __uint_as_float(wah[1]));
                wah[2] = tf32u(w2); wal[2] = tf32u(w2 - __uint_as_float(wah[2]));
                wah[3] = tf32u(w3); wal[3] = tf32u(w3 - __uint_as_float(wah[3]));
#pragma unroll
                for (int nf = 0; nf < 4; nf++) {
                    mma_tf32(bacc[si][nf], wah, bkh[nf]);
                    mma_tf32(bacc[si][nf], wal, bkh[nf]);
                    mma_tf32(bacc[si][nf], wah, bkl[nf]);
                }
            }
        }

        // ---- scale + mask, then struct-masked SSAN combine ----
#pragma unroll
        for (int nf = 0; nf < 4; nf++) {
            int c0 = wx * 32 + nf * 8 + 2 * tig;
            float2 mk = *(const float2*)&mask[b * L_ + kr0 + c0];
            sacc[nf][0] = sacc[nf][0] * 0.125f + mk.x;
            sacc[nf][1] = sacc[nf][1] * 0.125f + mk.y;
            sacc[nf][2] = sacc[nf][2] * 0.125f + mk.x;
            sacc[nf][3] = sacc[nf][3] * 0.125f + mk.y;
        }
#pragma unroll
        for (int si = 0; si < 5; si++) {
            const float2* sp = (const float2*)(strm +
                ((size_t)(si * B_ + b) * L_ + ql0) * L_ + kr0);
            const float abv = ab[si];
#pragma unroll
            for (int nf = 0; nf < 4; nf++) {
                int c0 = wx * 32 + nf * 8 + 2 * tig;
                float2 s0 = __ldg(&sp[r0 * 512 + (c0 >> 1)]);
                float2 s1 = __ldg(&sp[r1 * 512 + (c0 >> 1)]);
                sacc[nf][0] += (bacc[si][nf][0] + abv) * s0.x;
                sacc[nf][1] += (bacc[si][nf][1] + abv) * s0.y;
                sacc[nf][2] += (bacc[si][nf][2] + abv) * s1.x;
                sacc[nf][3] += (bacc[si][nf][3] + abv) * s1.y;
            }
        }

        // ---- partial row max ----
        {
            float m0v = -1e30f, m1v = -1e30f;
#pragma unroll
            for (int nf = 0; nf < 4; nf++) {
                m0v = fmaxf(m0v, fmaxf(sacc[nf][0], sacc[nf][1]));
                m1v = fmaxf(m1v, fmaxf(sacc[nf][2], sacc[nf][3]));
            }
            m0v = fmaxf(m0v, __shfl_xor_sync(0xffffffffu, m0v, 1));
            m0v = fmaxf(m0v, __shfl_xor_sync(0xffffffffu, m0v, 2));
            m1v = fmaxf(m1v, __shfl_xor_sync(0xffffffffu, m1v, 1));
            m1v = fmaxf(m1v, __shfl_xor_sync(0xffffffffu, m1v, 2));
            if (tig == 0) {
                sm[OFF_PM + wx * 64 + r0] = m0v;
                sm[OFF_PM + wx * 64 + r1] = m1v;
            }
        }
        __syncthreads();

        if (tid < 64) {
            float mo = sm[OFF_RM + tid];
            float mn = fmaxf(mo, fmaxf(sm[OFF_PM + tid], sm[OFF_PM + 64 + tid]));
            sm[OFF_RM + tid] = mn;
            sm[OFF_MB + tid] = mn;
            sm[OFF_FB + tid] = __expf(mo - mn);
        }
        __syncthreads();

        // ---- exp, split-P store (hi/lo), partial sums, O rescale ----
        {
            float mn0 = sm[OFF_MB + r0], mn1 = sm[OFF_MB + r1];
            float s0sum = 0.f, s1sum = 0.f;
#pragma unroll
            for (int nf = 0; nf < 4; nf++) {
                int c0 = wx * 32 + nf * 8 + 2 * tig;
                float p0 = __expf(sacc[nf][0] - mn0);
                float p1 = __expf(sacc[nf][1] - mn0);
                float p2 = __expf(sacc[nf][2] - mn1);
                float p3 = __expf(sacc[nf][3] - mn1);
                s0sum += p0 + p1;
                s1sum += p2 + p3;
                float h0 = tf32f(p0), h1 = tf32f(p1), h2 = tf32f(p2), h3 = tf32f(p3);
                *(float2*)&sm[OFF_PH + r0 * ST + c0] = make_float2(h0, h1);
                *(float2*)&sm[OFF_PH + r1 * ST + c0] = make_float2(h2, h3);
                *(float2*)&sm[OFF_PL + r0 * ST + c0] =
                    make_float2(tf32f(p0 - h0), tf32f(p1 - h1));
                *(float2*)&sm[OFF_PL + r1 * ST + c0] =
                    make_float2(tf32f(p2 - h2), tf32f(p3 - h3));
            }
            s0sum += __shfl_xor_sync(0xffffffffu, s0sum, 1);
            s0sum += __shfl_xor_sync(0xffffffffu, s0sum, 2);
            s1sum += __shfl_xor_sync(0xffffffffu, s1sum, 1);
            s1sum += __shfl_xor_sync(0xffffffffu, s1sum, 2);
            if (tig == 0) {
                sm[OFF_PS + wx * 64 + r0] = s0sum;
                sm[OFF_PS + wx * 64 + r1] = s1sum;
            }
            float f0 = sm[OFF_FB + r0], f1 = sm[OFF_FB + r1];
#pragma unroll
            for (int nf = 0; nf < 4; nf++) {
                o[nf][0] *= f0; o[nf][1] *= f0;
                o[nf][2] *= f1; o[nf][3] *= f1;
            }
        }
        __syncthreads();

        if (tid < 64)
            sm[OFF_RS + tid] = sm[OFF_RS + tid] * sm[OFF_FB + tid] +
                               sm[OFF_PS + tid] + sm[OFF_PS + 64 + tid];

        // ---- O += (Ph+Pl) @ (Vh+Vl)  (3-MMA split) ----
#pragma unroll
        for (int ks = 0; ks < 8; ks++) {
            unsigned pah[4], pal[4];
            int aa = OFF_PH + r0 * ST + ks * 8 + tig;
            pah[0] = __float_as_uint(sm[aa]);
            pah[1] = __float_as_uint(sm[aa + 8 * ST]);
            pah[2] = __float_as_uint(sm[aa + 4]);
            pah[3] = __float_as_uint(sm[aa + 8 * ST + 4]);
            int al = aa + (OFF_PL - OFF_PH);
            pal[0] = __float_as_uint(sm[al]);
            pal[1] = __float_as_uint(sm[al + 8 * ST]);
            pal[2] = __float_as_uint(sm[al + 4]);
            pal[3] = __float_as_uint(sm[al + 8 * ST + 4]);
#pragma unroll
            for (int nf = 0; nf < 4; nf++) {
                unsigned vbh[2], vbl[2];
                int na = OFF_VH + (ks * 8 + tig) * VST + wx * 32 + nf * 8 + gid;
                vbh[0] = __float_as_uint(sm[na]);
                vbh[1] = __float_as_uint(sm[na + 4 * VST]);
                int nl = na + (OFF_VL - OFF_VH);
                vbl[0] = __float_as_uint(sm[nl]);
                vbl[1] = __float_as_uint(sm[nl + 4 * VST]);
                mma_tf32(o[nf], pah, vbh);
                mma_tf32(o[nf], pal, vbh);
                mma_tf32(o[nf], pah, vbl);
            }
        }
    }
    __syncthreads();

    // ---- epilogue ----
    {
        float inv0 = 1.f / sm[OFF_RS + r0];
        float inv1 = 1.f / sm[OFF_RS + r1];
#pragma unroll
        for (int nf = 0; nf < 4; nf++) {
            int c0 = wx * 32 + nf * 8 + 2 * tig;
            *(float2*)&out[((size_t)(b * L_ + ql0 + r0)) * D_ + h * DH_ + c0] =
                make_float2(o[nf][0] * inv0, o[nf][1] * inv0);
            *(float2*)&out[((size_t)(b * L_ + ql0 + r1)) * D_ + h * DH_ + c0] =
                make_float2(o[nf][2] * inv1, o[nf][3] * inv1);
        }
    }
}

// ---------------------------------------------------------------------------
extern "C" void kernel_launch(void* const* d_in, const int* in_sizes, int n_in,
                              void* d_out, int out_size)
{
    const float* X    = (const float*)d_in[0];
    const float* mask = (const float*)d_in[1];
    const float* strm = (const float*)d_in[2];
    const float* Wq   = (const float*)d_in[3];
    const float* bq   = (const float*)d_in[4];
    const float* Wk   = (const float*)d_in[5];
    const float* bk   = (const float*)d_in[6];
    const float* Wv   = (const float*)d_in[7];
    const float* bv   = (const float*)d_in[8];
    const float* dist = (const float*)d_in[9];
    const float* ssan = (const float*)d_in[10];
    const float* ab   = (const float*)d_in[11];
    float* out = (float*)d_out;

    qkv_proj_kernel<<<dim3(6, 16, 3), 256>>>(X, Wq, bq, Wk, bk, Wv, bv);
    qw_proj_kernel<<<dim3(32, 12, 5), 256>>>(ssan);

    const int smem_bytes = SMEMF * (int)sizeof(float);
    cudaFuncSetAttribute(attn_mma_kernel, cudaFuncAttributeMaxDynamicSharedMemorySize, smem_bytes);
    attn_mma_kernel<<<dim3(16, 12, 2), 256, smem_bytes>>>(mask, strm, dist, ab, out);
}